// round 16
// baseline (speedup 1.0000x reference)
#include <cuda_runtime.h>
#include <cuda_bf16.h>
#include <cuda_fp16.h>
#include <cstdint>

#define MAXN 50000
#define D 128
#define SLOT_LG 7                      /* 128 slots per node */
#define SLOTS (1 << SLOT_LG)
#define TSTRIDE 136                    /* padded tile row stride in bf16 */
#define TROWB   (TSTRIDE * 2)          /* 272 bytes per tile row */
#define BM 64                          /* gemm block tile rows */
#define BN 64                          /* gemm block tile cols */
#define A_TILE_BYTES (BM * TROWB)      /* 17408 */
#define W_TILE_BYTES (BN * TROWB)      /* 17408 */

// ---- dynamic smem layout (bytes) ----
#define A_HI 0
#define A_LO (A_HI + A_TILE_BYTES)     /* 17408 */
#define W_HI (A_LO + A_TILE_BYTES)     /* 34816 */
#define W_LO (W_HI + W_TILE_BYTES)     /* 52224 */
#define RED_OFF (W_LO + W_TILE_BYTES)  /* 69632 */
#define SMEM_TOTAL (RED_OFF + 2048)    /* 71680 -> 3 blocks/SM */

// Scratch (no cudaMalloc allowed)
__device__ float g_buf0[MAXN * D];     // aggregated input / h2 raw
__device__ float g_buf1[MAXN * D];     // h1 raw
__device__ __half g_xh[MAXN * D];      // fp16 copy of x for the gather
__device__ __nv_bfloat16 g_Whi[2][D * D];   // W^T split-high, [n][k]
__device__ __nv_bfloat16 g_Wlo[2][D * D];   // W^T split-low,  [n][k]
__device__ float g_sum[2][D];
__device__ float g_sq[2][D];
__device__ int   g_is64;
// Direct bucketing: fixed 128 slots per node. g_cnt invariant: ZERO at entry
// (zero-init at module load; norm_kernel re-zeroes it at end of every run).
__device__ int g_cnt[MAXN];
__device__ int g_slots[MAXN * SLOTS];

// ---------------------------------------------------------------------------
static __device__ __forceinline__ uint32_t pack_bf2(__nv_bfloat16 a, __nv_bfloat16 b) {
    return (uint32_t)__bfloat16_as_ushort(a) |
           ((uint32_t)__bfloat16_as_ushort(b) << 16);
}
static __device__ __forceinline__ void mma16816(float* c, const uint32_t* a,
                                                const uint32_t* b) {
    asm volatile(
        "mma.sync.aligned.m16n8k16.row.col.f32.bf16.bf16.f32 "
        "{%0,%1,%2,%3}, {%4,%5,%6,%7}, {%8,%9}, {%0,%1,%2,%3};"
        : "+f"(c[0]), "+f"(c[1]), "+f"(c[2]), "+f"(c[3])
        : "r"(a[0]), "r"(a[1]), "r"(a[2]), "r"(a[3]), "r"(b[0]), "r"(b[1]));
}
static __device__ __forceinline__ void ldsm_x4(uint32_t* r, uint32_t addr) {
    asm volatile(
        "ldmatrix.sync.aligned.m8n8.x4.shared.b16 {%0,%1,%2,%3}, [%4];"
        : "=r"(r[0]), "=r"(r[1]), "=r"(r[2]), "=r"(r[3]) : "r"(addr));
}

// ---------------------------------------------------------------------------
// Setup: W split into bf16 hi/lo (coalesced reads), stats zero, x -> fp16,
// int-width detection (block 0 publishes g_is64).
__global__ void setup_kernel(const long long* __restrict__ ei, int E, int N,
                             const float* __restrict__ W1,
                             const float* __restrict__ W2,
                             const float* __restrict__ x, int total4) {
    int tid = threadIdx.x;
    int i = blockIdx.x * 256 + tid;

    if (i < 2 * D * D) {   // [L][k][n], n fastest -> coalesced W reads
        int L = i >> 14;
        int r = i & 16383;
        int k = r >> 7, n = r & 127;
        const float* W = L ? W2 : W1;
        float w = W[k * D + n];
        __nv_bfloat16 hi = __float2bfloat16(w);
        g_Whi[L][n * D + k] = hi;
        g_Wlo[L][n * D + k] = __float2bfloat16(w - __bfloat162float(hi));
    }
    if (i < 2 * D) {
        int p = i / D, c = i % D;
        g_sum[p][c] = 0.f;
        g_sq[p][c]  = 0.f;
    }
    if (i < total4) {      // x -> fp16 (4 elems/thread, coalesced)
        float4 v = __ldg((const float4*)x + i);
        __half2 h0 = __floats2half2_rn(v.x, v.y);
        __half2 h1 = __floats2half2_rn(v.z, v.w);
        uint2 o;
        o.x = *(uint32_t*)&h0;
        o.y = *(uint32_t*)&h1;
        *((uint2*)g_xh + i) = o;
    }
    if (blockIdx.x == 0) {   // int64-vs-int32 detection (JAX x64 ambiguity)
        __shared__ int bad;
        if (tid == 0) bad = 0;
        __syncthreads();
        int M = min(E, 4096);
        for (int t = tid; t < M; t += 256) {
            long long v = __ldg(ei + t);
            if (v < 0 || v >= (long long)N) bad = 1;
        }
        __syncthreads();
        if (tid == 0) g_is64 = bad ? 0 : 1;
    }
}

// ---------------------------------------------------------------------------
// Direct bucketing: 1 edge/thread, append src into dst's fixed slot array.
__global__ void bucket_kernel(const void* __restrict__ ei_raw, int E) {
    int e = blockIdx.x * blockDim.x + threadIdx.x;
    if (e >= E) return;
    int s, d;
    if (g_is64) {
        const long long* p = (const long long*)ei_raw;
        s = (int)__ldg(p + e); d = (int)__ldg(p + E + e);
    } else {
        const int* p = (const int*)ei_raw;
        s = __ldg(p + e); d = __ldg(p + E + e);
    }
    int pos = atomicAdd(&g_cnt[d], 1);
    if (pos < SLOTS) g_slots[(d << SLOT_LG) + pos] = s;
}

// ---------------------------------------------------------------------------
// One warp per node: g_buf0[n] = (1+eps)*x[n] (fp32) + sum of fp16 neighbor
// rows (fp32 accumulation), neighbors from the node's slot array.
__global__ void aggregate_kernel(const float* __restrict__ x,
                                 const float* __restrict__ eps, int N) {
    int warp = (blockIdx.x * blockDim.x + threadIdx.x) >> 5;
    if (warp >= N) return;
    int lane = threadIdx.x & 31;
    float sc = 1.0f + eps[0];
    float4 acc = __ldg((const float4*)(x + (size_t)warp * D) + lane);
    acc.x *= sc; acc.y *= sc; acc.z *= sc; acc.w *= sc;

    const uint2* xh = (const uint2*)g_xh;       // 32 uint2 per row
    const int* slots = g_slots + ((size_t)warp << SLOT_LG);
    int cnt = g_cnt[warp];
    if (cnt > SLOTS) cnt = SLOTS;               // impossible-case OOB guard

    for (int c = 0; c < cnt; c += 32) {
        int n = min(32, cnt - c);
        int myv = (c + lane < cnt) ? __ldg(&slots[c + lane]) : 0;
        int j = 0;
        for (; j + 4 <= n; j += 4) {
            int s0 = __shfl_sync(0xffffffffu, myv, j);
            int s1 = __shfl_sync(0xffffffffu, myv, j + 1);
            int s2 = __shfl_sync(0xffffffffu, myv, j + 2);
            int s3 = __shfl_sync(0xffffffffu, myv, j + 3);
            uint2 r0 = __ldg(xh + (size_t)s0 * 32 + lane);
            uint2 r1 = __ldg(xh + (size_t)s1 * 32 + lane);
            uint2 r2 = __ldg(xh + (size_t)s2 * 32 + lane);
            uint2 r3 = __ldg(xh + (size_t)s3 * 32 + lane);
#pragma unroll
            for (int t = 0; t < 4; t++) {
                uint2 r = t == 0 ? r0 : t == 1 ? r1 : t == 2 ? r2 : r3;
                float2 f0 = __half22float2(*(__half2*)&r.x);
                float2 f1 = __half22float2(*(__half2*)&r.y);
                acc.x += f0.x; acc.y += f0.y; acc.z += f1.x; acc.w += f1.y;
            }
        }
        for (; j < n; j++) {
            int s0 = __shfl_sync(0xffffffffu, myv, j);
            uint2 r = __ldg(xh + (size_t)s0 * 32 + lane);
            float2 f0 = __half22float2(*(__half2*)&r.x);
            float2 f1 = __half22float2(*(__half2*)&r.y);
            acc.x += f0.x; acc.y += f0.y; acc.z += f1.x; acc.w += f1.y;
        }
    }
    ((float4*)(g_buf0 + (size_t)warp * D))[lane] = acc;
}

// ---------------------------------------------------------------------------
// Tensor-core GEMM via mma.sync + ldmatrix: out = op(A) @ W^T + bias.
// Split-bf16: D = Ahi*Whi + Ahi*Wlo + Alo*Whi, fp32 register accumulators.
// Block tile 64x64 (71.7KB smem -> 3 blocks/SM), 8 warps (2x4),
// warp tile 32x16, K=128. blockIdx: bm = >>1 (rows), bn = &1 (64-col slice).
// normPhase>=0: A rows = relu(bn(A)) with bn params computed per-block.
// Output BN stats for this block's 64 columns accumulated in the epilogue.
__global__ void __launch_bounds__(256)
gemm_tc(const float* __restrict__ A, int layer, const float* __restrict__ bias,
        float* __restrict__ out, int N, int phase, int normPhase,
        const float* __restrict__ gamma, const float* __restrict__ beta,
        float invN) {
    extern __shared__ char smem[];
    int tid = threadIdx.x, wid = tid >> 5, lane = tid & 31;
    int gq = lane >> 2;          // groupID 0..7
    int q  = lane & 3;           // threadID-in-group 0..3
    int warpM = wid >> 2;        // 0..1 (32-row halves)
    int warpN = wid & 3;         // 0..3 (16-col slices)
    int rowStart = (blockIdx.x >> 1) * BM;
    int colStart = (blockIdx.x & 1) * BN;

    const __nv_bfloat16* Whi = g_Whi[layer];
    const __nv_bfloat16* Wlo = g_Wlo[layer];

    // BN scale/shift of the INPUT (k-dim, all 128), computed per-block.
    float* nsc = (float*)(smem + RED_OFF);       // [128]
    float* nsh = nsc + 128;                      // [128]
    if (normPhase >= 0 && tid < 128) {
        float mu  = g_sum[normPhase][tid] * invN;
        float var = g_sq[normPhase][tid] * invN - mu * mu;
        float inv = rsqrtf(var + 1e-5f);
        float sc  = __ldg(&gamma[tid]) * inv;
        nsc[tid] = sc;
        nsh[tid] = __ldg(&beta[tid]) - mu * sc;
    }
    __syncthreads();

    // --- A tile (64x128): load fp32, (norm+relu), split bf16 hi/lo.
#pragma unroll
    for (int l = 0; l < 8; l++) {
        int idx = tid + 256 * l;
        int row = idx >> 5, c4 = idx & 31;
        int gr = rowStart + row;
        float4 v = make_float4(0.f, 0.f, 0.f, 0.f);
        if (gr < N) v = __ldg((const float4*)(A + (size_t)gr * D) + c4);
        if (normPhase >= 0) {
            float4 sc = ((const float4*)nsc)[c4];
            float4 sh = ((const float4*)nsh)[c4];
            v.x = fmaxf(fmaf(v.x, sc.x, sh.x), 0.f);
            v.y = fmaxf(fmaf(v.y, sc.y, sh.y), 0.f);
            v.z = fmaxf(fmaf(v.z, sc.z, sh.z), 0.f);
            v.w = fmaxf(fmaf(v.w, sc.w, sh.w), 0.f);
        }
        __nv_bfloat16 hx = __float2bfloat16(v.x), hy = __float2bfloat16(v.y);
        __nv_bfloat16 hz = __float2bfloat16(v.z), hw = __float2bfloat16(v.w);
        uint2 hi2, lo2;
        hi2.x = pack_bf2(hx, hy);
        hi2.y = pack_bf2(hz, hw);
        lo2.x = pack_bf2(__float2bfloat16(v.x - __bfloat162float(hx)),
                         __float2bfloat16(v.y - __bfloat162float(hy)));
        lo2.y = pack_bf2(__float2bfloat16(v.z - __bfloat162float(hz)),
                         __float2bfloat16(v.w - __bfloat162float(hw)));
        uint32_t off = row * TROWB + c4 * 8;
        *(uint2*)(smem + A_HI + off) = hi2;
        *(uint2*)(smem + A_LO + off) = lo2;
    }
    // --- W tiles (64x128 slice [colStart, colStart+64)): bf16 [n][k].
#pragma unroll
    for (int l = 0; l < 8; l++) {
        int idx = tid + 256 * l;
        int nl = idx >> 5, c4 = idx & 31;
        int n = colStart + nl;
        uint32_t off = nl * TROWB + c4 * 8;
        *(uint2*)(smem + W_HI + off) = *(const uint2*)(Whi + n * D + c4 * 4);
        *(uint2*)(smem + W_LO + off) = *(const uint2*)(Wlo + n * D + c4 * 4);
    }
    __syncthreads();

    float acc[2][2][4];
#pragma unroll
    for (int mt = 0; mt < 2; mt++)
#pragma unroll
        for (int nt = 0; nt < 2; nt++)
#pragma unroll
            for (int r = 0; r < 4; r++) acc[mt][nt][r] = 0.f;

    // ldmatrix per-lane base addresses.
    uint32_t sbase = (uint32_t)__cvta_generic_to_shared(smem);
    // A x4: lanes 0-7 row-lo/k-lo, 8-15 row-hi/k-lo, 16-23 row-lo/k-hi,
    //       24-31 row-hi/k-hi  (rows via lane&15, k half via lane>>4)
    uint32_t aAddr = sbase + A_HI
                   + (warpM * 32 + (lane & 15)) * TROWB + (lane >> 4) * 16;
    // B x4: lanes 0-7 nt0/k-lo, 8-15 nt0/k-hi, 16-23 nt1/k-lo, 24-31 nt1/k-hi
    uint32_t bAddr = sbase + W_HI
                   + (warpN * 16 + (lane >> 4) * 8 + (lane & 7)) * TROWB
                   + ((lane >> 3) & 1) * 16;

#pragma unroll 1
    for (int pass = 0; pass < 3; pass++) {
        uint32_t aP = aAddr + ((pass == 2) ? (uint32_t)A_TILE_BYTES : 0u);
        uint32_t bP = bAddr + ((pass == 1) ? (uint32_t)W_TILE_BYTES : 0u);
#pragma unroll
        for (int ks = 0; ks < 8; ks++) {
            uint32_t a0[4], a1[4], b[4];
            ldsm_x4(a0, aP + ks * 32);
            ldsm_x4(a1, aP + 16 * TROWB + ks * 32);
            ldsm_x4(b,  bP + ks * 32);
            mma16816(acc[0][0], a0, b);
            mma16816(acc[0][1], a0, b + 2);
            mma16816(acc[1][0], a1, b);
            mma16816(acc[1][1], a1, b + 2);
        }
    }

    // --- Epilogue: bias, store, BN stats (this block's 64 columns).
    float s[2][2], qs[2][2];
#pragma unroll
    for (int nt = 0; nt < 2; nt++)
        s[nt][0] = s[nt][1] = qs[nt][0] = qs[nt][1] = 0.f;

#pragma unroll
    for (int nt = 0; nt < 2; nt++) {
        int cbase = colStart + warpN * 16 + nt * 8 + q * 2;
        float b0 = __ldg(&bias[cbase]), b1 = __ldg(&bias[cbase + 1]);
#pragma unroll
        for (int mt = 0; mt < 2; mt++) {
            int r0 = rowStart + warpM * 32 + mt * 16 + gq;
            int r1 = r0 + 8;
            float h0 = acc[mt][nt][0] + b0, h1 = acc[mt][nt][1] + b1;
            float h2 = acc[mt][nt][2] + b0, h3 = acc[mt][nt][3] + b1;
            if (r0 < N) {
                *(float2*)(out + (size_t)r0 * D + cbase) = make_float2(h0, h1);
                s[nt][0] += h0; s[nt][1] += h1;
                qs[nt][0] += h0 * h0; qs[nt][1] += h1 * h1;
            }
            if (r1 < N) {
                *(float2*)(out + (size_t)r1 * D + cbase) = make_float2(h2, h3);
                s[nt][0] += h2; s[nt][1] += h3;
                qs[nt][0] += h2 * h2; qs[nt][1] += h3 * h3;
            }
        }
    }
    // reduce across groupID lanes (same columns): xor 4, 8, 16
#pragma unroll
    for (int m = 4; m <= 16; m <<= 1)
#pragma unroll
        for (int nt = 0; nt < 2; nt++) {
            s[nt][0]  += __shfl_xor_sync(0xffffffffu, s[nt][0],  m);
            s[nt][1]  += __shfl_xor_sync(0xffffffffu, s[nt][1],  m);
            qs[nt][0] += __shfl_xor_sync(0xffffffffu, qs[nt][0], m);
            qs[nt][1] += __shfl_xor_sync(0xffffffffu, qs[nt][1], m);
        }
    float* red = (float*)(smem + RED_OFF);     // [2][8 wid][16 cols]
    __syncthreads();
    if (lane < 4) {
#pragma unroll
        for (int nt = 0; nt < 2; nt++) {
            red[wid * 16 + nt * 8 + lane * 2]           = s[nt][0];
            red[wid * 16 + nt * 8 + lane * 2 + 1]       = s[nt][1];
            red[128 + wid * 16 + nt * 8 + lane * 2]     = qs[nt][0];
            red[128 + wid * 16 + nt * 8 + lane * 2 + 1] = qs[nt][1];
        }
    }
    __syncthreads();
    // column c gets contributions from wid = (c>>4) and (c>>4)+4
    if (tid < 64) {
        atomicAdd(&g_sum[phase][colStart + tid], red[tid] + red[tid + 64]);
    } else if (tid < 128) {
        int c = tid - 64;
        atomicAdd(&g_sq[phase][colStart + c], red[128 + c] + red[128 + c + 64]);
    }
}

// ---------------------------------------------------------------------------
// out = relu(bn(h)); bn params per-block. Also re-zeroes g_cnt (invariant).
__global__ void norm_kernel(const float* __restrict__ h, int phase,
                            const float* __restrict__ gamma,
                            const float* __restrict__ beta, float invN,
                            float* __restrict__ extout, int total4, int N) {
    __shared__ float nsc[D], nsh[D];
    int tid = threadIdx.x;
    if (tid < D) {
        float mu  = g_sum[phase][tid] * invN;
        float var = g_sq[phase][tid] * invN - mu * mu;
        float inv = rsqrtf(var + 1e-5f);
        float sc  = __ldg(&gamma[tid]) * inv;
        nsc[tid] = sc;
        nsh[tid] = __ldg(&beta[tid]) - mu * sc;
    }
    __syncthreads();
    int i = blockIdx.x * blockDim.x + tid;
    if (i < N) g_cnt[i] = 0;            // restore invariant for next run
    if (i >= total4) return;
    int c4 = i & 31;
    float4 v  = ((const float4*)h)[i];
    float4 sc = ((const float4*)nsc)[c4];
    float4 sh = ((const float4*)nsh)[c4];
    float4 o;
    o.x = fmaxf(v.x * sc.x + sh.x, 0.f);
    o.y = fmaxf(v.y * sc.y + sh.y, 0.f);
    o.z = fmaxf(v.z * sc.z + sh.z, 0.f);
    o.w = fmaxf(v.w * sc.w + sh.w, 0.f);
    ((float4*)extout)[i] = o;
}

// ---------------------------------------------------------------------------
extern "C" void kernel_launch(void* const* d_in, const int* in_sizes, int n_in,
                              void* d_out, int out_size) {
    const float* x   = (const float*)d_in[0];
    const void*  ei  = d_in[1];
    const float* eps = (const float*)d_in[2];
    const float* W1  = (const float*)d_in[3];
    const float* b1  = (const float*)d_in[4];
    const float* g1  = (const float*)d_in[5];
    const float* be1 = (const float*)d_in[6];
    const float* W2  = (const float*)d_in[7];
    const float* b2  = (const float*)d_in[8];
    const float* g2  = (const float*)d_in[9];
    const float* be2 = (const float*)d_in[10];

    int N = in_sizes[0] / D;
    int E = in_sizes[1] / 2;
    int total4 = N * (D / 4);
    const int TB = 256;

    float* buf0;
    float* buf1;
    cudaGetSymbolAddress((void**)&buf0, g_buf0);
    cudaGetSymbolAddress((void**)&buf1, g_buf1);

    cudaFuncSetAttribute(gemm_tc, cudaFuncAttributeMaxDynamicSharedMemorySize,
                         SMEM_TOTAL);

    int xblk = (total4 + 255) / 256;        // x->fp16 conversion coverage
    int sblk = xblk > 128 ? xblk : 128;     // also covers W split

    setup_kernel<<<sblk, 256>>>((const long long*)ei, E, N, W1, W2, x, total4);
    bucket_kernel<<<(E + 255) / 256, 256>>>(ei, E);
    aggregate_kernel<<<(N * 32 + TB - 1) / TB, TB>>>(x, eps, N);

    int gblocks = ((N + BM - 1) / BM) * 2;   // x2: 64-column slices
    float invN = 1.0f / (float)N;

    // layer 1: h1 = g_buf0 @ W1 + b1 (stats fused)
    gemm_tc<<<gblocks, 256, SMEM_TOTAL>>>(buf0, 0, b1, buf1, N, 0, -1,
                                          nullptr, nullptr, invN);
    // layer 2: h2 = relu(bn(h1)) @ W2 + b2 (bn params from g_sum[0] per-block)
    gemm_tc<<<gblocks, 256, SMEM_TOTAL>>>(buf1, 1, b2, buf0, N, 1, 0,
                                          g1, be1, invN);
    // final: d_out = relu(bn(h2)) + g_cnt re-zero
    norm_kernel<<<(total4 + TB - 1) / TB, TB>>>(buf0, 1, g2, be2, invN,
                                                (float*)d_out, total4, N);
}

// round 17
// speedup vs baseline: 1.1142x; 1.1142x over previous
#include <cuda_runtime.h>
#include <cuda_bf16.h>
#include <cuda_fp16.h>
#include <cstdint>

#define MAXN 50000
#define D 128
#define SLOT_LG 7                      /* 128 slots per node */
#define SLOTS (1 << SLOT_LG)
#define TSTRIDE 136                    /* padded tile row stride in bf16 */
#define TROWB   (TSTRIDE * 2)          /* 272 bytes per tile row */
#define BM 64                          /* gemm block tile rows */
#define A_TILE_BYTES (BM * TROWB)      /* 17408 */
#define W_TILE_BYTES (128 * TROWB)     /* 34816 */

// ---- dynamic smem layout (bytes) ----
#define A_HI 0
#define A_LO (A_HI + A_TILE_BYTES)     /* 17408 */
#define W_HI (A_LO + A_TILE_BYTES)     /* 34816 */
#define W_LO (W_HI + W_TILE_BYTES)     /* 69632 */
#define RED_OFF (W_LO + W_TILE_BYTES)  /* 104448: 512 floats */
#define SMEM_TOTAL (RED_OFF + 2048)    /* 106496 -> 2 blocks/SM */

// Scratch (no cudaMalloc allowed)
__device__ float g_buf0[MAXN * D];     // aggregated input / h2 raw
__device__ float g_buf1[MAXN * D];     // h1 raw
__device__ __half g_xh[MAXN * D];      // fp16 copy of x for the gather
__device__ __nv_bfloat16 g_Whi[2][D * D];   // W^T split-high, [n][k]
__device__ __nv_bfloat16 g_Wlo[2][D * D];   // W^T split-low,  [n][k]
__device__ float g_sum[2][D];
__device__ float g_sq[2][D];
__device__ int   g_is64;
// Direct bucketing: fixed 128 slots per node. g_cnt invariant: ZERO at entry
// (zero-init at module load; norm_kernel re-zeroes it at end of every run).
__device__ int g_cnt[MAXN];
__device__ int g_slots[MAXN * SLOTS];

// ---------------------------------------------------------------------------
static __device__ __forceinline__ uint32_t pack_bf2(__nv_bfloat16 a, __nv_bfloat16 b) {
    return (uint32_t)__bfloat16_as_ushort(a) |
           ((uint32_t)__bfloat16_as_ushort(b) << 16);
}
static __device__ __forceinline__ void mma16816(float* c, const uint32_t* a,
                                                const uint32_t* b) {
    asm volatile(
        "mma.sync.aligned.m16n8k16.row.col.f32.bf16.bf16.f32 "
        "{%0,%1,%2,%3}, {%4,%5,%6,%7}, {%8,%9}, {%0,%1,%2,%3};"
        : "+f"(c[0]), "+f"(c[1]), "+f"(c[2]), "+f"(c[3])
        : "r"(a[0]), "r"(a[1]), "r"(a[2]), "r"(a[3]), "r"(b[0]), "r"(b[1]));
}
static __device__ __forceinline__ void ldsm_x4(uint32_t* r, uint32_t addr) {
    asm volatile(
        "ldmatrix.sync.aligned.m8n8.x4.shared.b16 {%0,%1,%2,%3}, [%4];"
        : "=r"(r[0]), "=r"(r[1]), "=r"(r[2]), "=r"(r[3]) : "r"(addr));
}

// ---------------------------------------------------------------------------
// Setup: W split into bf16 hi/lo (coalesced reads), stats zero, x -> fp16,
// int-width detection (block 0 publishes g_is64).
__global__ void setup_kernel(const long long* __restrict__ ei, int E, int N,
                             const float* __restrict__ W1,
                             const float* __restrict__ W2,
                             const float* __restrict__ x, int total4) {
    int tid = threadIdx.x;
    int i = blockIdx.x * 256 + tid;

    if (i < 2 * D * D) {   // [L][k][n], n fastest -> coalesced W reads
        int L = i >> 14;
        int r = i & 16383;
        int k = r >> 7, n = r & 127;
        const float* W = L ? W2 : W1;
        float w = W[k * D + n];
        __nv_bfloat16 hi = __float2bfloat16(w);
        g_Whi[L][n * D + k] = hi;
        g_Wlo[L][n * D + k] = __float2bfloat16(w - __bfloat162float(hi));
    }
    if (i < 2 * D) {
        int p = i / D, c = i % D;
        g_sum[p][c] = 0.f;
        g_sq[p][c]  = 0.f;
    }
    if (i < total4) {      // x -> fp16 (4 elems/thread, coalesced)
        float4 v = __ldg((const float4*)x + i);
        __half2 h0 = __floats2half2_rn(v.x, v.y);
        __half2 h1 = __floats2half2_rn(v.z, v.w);
        uint2 o;
        o.x = *(uint32_t*)&h0;
        o.y = *(uint32_t*)&h1;
        *((uint2*)g_xh + i) = o;
    }
    if (blockIdx.x == 0) {   // int64-vs-int32 detection (JAX x64 ambiguity)
        __shared__ int bad;
        if (tid == 0) bad = 0;
        __syncthreads();
        int M = min(E, 4096);
        for (int t = tid; t < M; t += 256) {
            long long v = __ldg(ei + t);
            if (v < 0 || v >= (long long)N) bad = 1;
        }
        __syncthreads();
        if (tid == 0) g_is64 = bad ? 0 : 1;
    }
}

// ---------------------------------------------------------------------------
// Direct bucketing: 1 edge/thread, append src into dst's fixed slot array.
__global__ void bucket_kernel(const void* __restrict__ ei_raw, int E) {
    int e = blockIdx.x * blockDim.x + threadIdx.x;
    if (e >= E) return;
    int s, d;
    if (g_is64) {
        const long long* p = (const long long*)ei_raw;
        s = (int)__ldg(p + e); d = (int)__ldg(p + E + e);
    } else {
        const int* p = (const int*)ei_raw;
        s = __ldg(p + e); d = __ldg(p + E + e);
    }
    int pos = atomicAdd(&g_cnt[d], 1);
    if (pos < SLOTS) g_slots[(d << SLOT_LG) + pos] = s;
}

// ---------------------------------------------------------------------------
// One warp per node: g_buf0[n] = (1+eps)*x[n] (fp32) + sum of fp16 neighbor
// rows (fp32 accumulation), neighbors from the node's slot array.
__global__ void aggregate_kernel(const float* __restrict__ x,
                                 const float* __restrict__ eps, int N) {
    int warp = (blockIdx.x * blockDim.x + threadIdx.x) >> 5;
    if (warp >= N) return;
    int lane = threadIdx.x & 31;
    float sc = 1.0f + eps[0];
    float4 acc = __ldg((const float4*)(x + (size_t)warp * D) + lane);
    acc.x *= sc; acc.y *= sc; acc.z *= sc; acc.w *= sc;

    const uint2* xh = (const uint2*)g_xh;       // 32 uint2 per row
    const int* slots = g_slots + ((size_t)warp << SLOT_LG);
    int cnt = g_cnt[warp];
    if (cnt > SLOTS) cnt = SLOTS;               // impossible-case OOB guard

    for (int c = 0; c < cnt; c += 32) {
        int n = min(32, cnt - c);
        int myv = (c + lane < cnt) ? __ldg(&slots[c + lane]) : 0;
        int j = 0;
        for (; j + 4 <= n; j += 4) {
            int s0 = __shfl_sync(0xffffffffu, myv, j);
            int s1 = __shfl_sync(0xffffffffu, myv, j + 1);
            int s2 = __shfl_sync(0xffffffffu, myv, j + 2);
            int s3 = __shfl_sync(0xffffffffu, myv, j + 3);
            uint2 r0 = __ldg(xh + (size_t)s0 * 32 + lane);
            uint2 r1 = __ldg(xh + (size_t)s1 * 32 + lane);
            uint2 r2 = __ldg(xh + (size_t)s2 * 32 + lane);
            uint2 r3 = __ldg(xh + (size_t)s3 * 32 + lane);
#pragma unroll
            for (int t = 0; t < 4; t++) {
                uint2 r = t == 0 ? r0 : t == 1 ? r1 : t == 2 ? r2 : r3;
                float2 f0 = __half22float2(*(__half2*)&r.x);
                float2 f1 = __half22float2(*(__half2*)&r.y);
                acc.x += f0.x; acc.y += f0.y; acc.z += f1.x; acc.w += f1.y;
            }
        }
        for (; j < n; j++) {
            int s0 = __shfl_sync(0xffffffffu, myv, j);
            uint2 r = __ldg(xh + (size_t)s0 * 32 + lane);
            float2 f0 = __half22float2(*(__half2*)&r.x);
            float2 f1 = __half22float2(*(__half2*)&r.y);
            acc.x += f0.x; acc.y += f0.y; acc.z += f1.x; acc.w += f1.y;
        }
    }
    ((float4*)(g_buf0 + (size_t)warp * D))[lane] = acc;
}

// ---------------------------------------------------------------------------
// Tensor-core GEMM via mma.sync + ldmatrix: out = op(A) @ W^T + bias.
// Split-bf16: D = Ahi*Whi + Ahi*Wlo + Alo*Whi, fp32 register accumulators.
// Block tile 64x128 (106.5KB smem -> 2 blocks/SM), 8 warps (2x4),
// warp tile 32x32, K=128. Mainloop fragments loaded with ldmatrix.x4.
// normPhase>=0: A rows = relu(bn(A)) with bn params computed per-block.
// Output BN stats accumulated into g_sum/g_sq[phase] in the epilogue.
__global__ void __launch_bounds__(256)
gemm_tc(const float* __restrict__ A, int layer, const float* __restrict__ bias,
        float* __restrict__ out, int N, int phase, int normPhase,
        const float* __restrict__ gamma, const float* __restrict__ beta,
        float invN) {
    extern __shared__ char smem[];
    int tid = threadIdx.x, wid = tid >> 5, lane = tid & 31;
    int gq = lane >> 2;          // groupID 0..7
    int q  = lane & 3;           // threadID-in-group 0..3
    int warpM = wid >> 2;        // 0..1 (32-row halves)
    int warpN = wid & 3;         // 0..3 (32-col slices)
    int rowStart = blockIdx.x * BM;

    const __nv_bfloat16* Whi = g_Whi[layer];
    const __nv_bfloat16* Wlo = g_Wlo[layer];

    // BN scale/shift of the INPUT, computed per-block.
    float* nsc = (float*)(smem + RED_OFF);       // [128]
    float* nsh = nsc + 128;                      // [128]
    if (normPhase >= 0 && tid < 128) {
        float mu  = g_sum[normPhase][tid] * invN;
        float var = g_sq[normPhase][tid] * invN - mu * mu;
        float inv = rsqrtf(var + 1e-5f);
        float sc  = __ldg(&gamma[tid]) * inv;
        nsc[tid] = sc;
        nsh[tid] = __ldg(&beta[tid]) - mu * sc;
    }
    __syncthreads();

    // --- A tile (64x128): load fp32, (norm+relu), split bf16 hi/lo.
#pragma unroll
    for (int l = 0; l < 8; l++) {
        int idx = tid + 256 * l;
        int row = idx >> 5, c4 = idx & 31;
        int gr = rowStart + row;
        float4 v = make_float4(0.f, 0.f, 0.f, 0.f);
        if (gr < N) v = __ldg((const float4*)(A + (size_t)gr * D) + c4);
        if (normPhase >= 0) {
            float4 sc = ((const float4*)nsc)[c4];
            float4 sh = ((const float4*)nsh)[c4];
            v.x = fmaxf(fmaf(v.x, sc.x, sh.x), 0.f);
            v.y = fmaxf(fmaf(v.y, sc.y, sh.y), 0.f);
            v.z = fmaxf(fmaf(v.z, sc.z, sh.z), 0.f);
            v.w = fmaxf(fmaf(v.w, sc.w, sh.w), 0.f);
        }
        __nv_bfloat16 hx = __float2bfloat16(v.x), hy = __float2bfloat16(v.y);
        __nv_bfloat16 hz = __float2bfloat16(v.z), hw = __float2bfloat16(v.w);
        uint2 hi2, lo2;
        hi2.x = pack_bf2(hx, hy);
        hi2.y = pack_bf2(hz, hw);
        lo2.x = pack_bf2(__float2bfloat16(v.x - __bfloat162float(hx)),
                         __float2bfloat16(v.y - __bfloat162float(hy)));
        lo2.y = pack_bf2(__float2bfloat16(v.z - __bfloat162float(hz)),
                         __float2bfloat16(v.w - __bfloat162float(hw)));
        uint32_t off = row * TROWB + c4 * 8;
        *(uint2*)(smem + A_HI + off) = hi2;
        *(uint2*)(smem + A_LO + off) = lo2;
    }
    // --- W tiles (128x128): pre-split bf16 [n][k] -> padded smem.
#pragma unroll
    for (int l = 0; l < 16; l++) {
        int idx = tid + 256 * l;
        int n = idx >> 5, c4 = idx & 31;
        uint32_t off = n * TROWB + c4 * 8;
        *(uint2*)(smem + W_HI + off) = *(const uint2*)(Whi + n * D + c4 * 4);
        *(uint2*)(smem + W_LO + off) = *(const uint2*)(Wlo + n * D + c4 * 4);
    }
    __syncthreads();

    float acc[2][4][4];
#pragma unroll
    for (int mt = 0; mt < 2; mt++)
#pragma unroll
        for (int nt = 0; nt < 4; nt++)
#pragma unroll
            for (int r = 0; r < 4; r++) acc[mt][nt][r] = 0.f;

    // ldmatrix per-lane base addresses.
    uint32_t sbase = (uint32_t)__cvta_generic_to_shared(smem);
    // A x4: lanes 0-15 -> rows (lane&15) of the 16-row tile, k-lo;
    //       lanes 16-31 -> same rows, k-hi (+16B). Covers one m16k16 tile.
    uint32_t aAddr = sbase + A_HI
                   + (warpM * 32 + (lane & 15)) * TROWB + (lane >> 4) * 16;
    // B x4: lanes 0-7 n-rows 0-7 k-lo, 8-15 same rows k-hi,
    //       16-23 n-rows 8-15 k-lo, 24-31 k-hi. Covers 2 n8k16 tiles.
    uint32_t bAddr = sbase + W_HI
                   + (warpN * 32 + (lane >> 4) * 8 + (lane & 7)) * TROWB
                   + ((lane >> 3) & 1) * 16;

#pragma unroll 1
    for (int pass = 0; pass < 3; pass++) {
        uint32_t aP = aAddr;
        uint32_t bP = bAddr;
        if (pass == 2) aP += (uint32_t)A_TILE_BYTES;
        if (pass == 1) bP += (uint32_t)W_TILE_BYTES;
#pragma unroll
        for (int ks = 0; ks < 8; ks++) {
            uint32_t a0[4], a1[4], b01[4], b23[4];
            ldsm_x4(a0, aP + ks * 32);
            ldsm_x4(a1, aP + 16 * TROWB + ks * 32);
            ldsm_x4(b01, bP + ks * 32);
            ldsm_x4(b23, bP + 16 * TROWB + ks * 32);
            mma16816(acc[0][0], a0, b01);
            mma16816(acc[0][1], a0, b01 + 2);
            mma16816(acc[0][2], a0, b23);
            mma16816(acc[0][3], a0, b23 + 2);
            mma16816(acc[1][0], a1, b01);
            mma16816(acc[1][1], a1, b01 + 2);
            mma16816(acc[1][2], a1, b23);
            mma16816(acc[1][3], a1, b23 + 2);
        }
    }

    // --- Epilogue: bias, store, BN stats.
    float s[4][2], qs[4][2];
#pragma unroll
    for (int nt = 0; nt < 4; nt++)
        s[nt][0] = s[nt][1] = qs[nt][0] = qs[nt][1] = 0.f;

#pragma unroll
    for (int nt = 0; nt < 4; nt++) {
        int cbase = warpN * 32 + nt * 8 + q * 2;
        float b0 = __ldg(&bias[cbase]), b1 = __ldg(&bias[cbase + 1]);
#pragma unroll
        for (int mt = 0; mt < 2; mt++) {
            int r0 = rowStart + warpM * 32 + mt * 16 + gq;
            int r1 = r0 + 8;
            float h0 = acc[mt][nt][0] + b0, h1 = acc[mt][nt][1] + b1;
            float h2 = acc[mt][nt][2] + b0, h3 = acc[mt][nt][3] + b1;
            if (r0 < N) {
                *(float2*)(out + (size_t)r0 * D + cbase) = make_float2(h0, h1);
                s[nt][0] += h0; s[nt][1] += h1;
                qs[nt][0] += h0 * h0; qs[nt][1] += h1 * h1;
            }
            if (r1 < N) {
                *(float2*)(out + (size_t)r1 * D + cbase) = make_float2(h2, h3);
                s[nt][0] += h2; s[nt][1] += h3;
                qs[nt][0] += h2 * h2; qs[nt][1] += h3 * h3;
            }
        }
    }
    // reduce across groupID lanes (same columns): xor 4, 8, 16
#pragma unroll
    for (int m = 4; m <= 16; m <<= 1)
#pragma unroll
        for (int nt = 0; nt < 4; nt++) {
            s[nt][0]  += __shfl_xor_sync(0xffffffffu, s[nt][0],  m);
            s[nt][1]  += __shfl_xor_sync(0xffffffffu, s[nt][1],  m);
            qs[nt][0] += __shfl_xor_sync(0xffffffffu, qs[nt][0], m);
            qs[nt][1] += __shfl_xor_sync(0xffffffffu, qs[nt][1], m);
        }
    float* red = (float*)(smem + RED_OFF);     // [2][8 warps][32]
    __syncthreads();
    if (lane < 4) {
#pragma unroll
        for (int nt = 0; nt < 4; nt++) {
            red[wid * 32 + nt * 8 + lane * 2]           = s[nt][0];
            red[wid * 32 + nt * 8 + lane * 2 + 1]       = s[nt][1];
            red[256 + wid * 32 + nt * 8 + lane * 2]     = qs[nt][0];
            red[256 + wid * 32 + nt * 8 + lane * 2 + 1] = qs[nt][1];
        }
    }
    __syncthreads();
    if (tid < 128) {
        atomicAdd(&g_sum[phase][tid], red[tid] + red[tid + 128]);
    } else {
        int c = tid - 128;
        atomicAdd(&g_sq[phase][c], red[256 + c] + red[256 + c + 128]);
    }
}

// ---------------------------------------------------------------------------
// out = relu(bn(h)); bn params per-block. Also re-zeroes g_cnt (invariant).
__global__ void norm_kernel(const float* __restrict__ h, int phase,
                            const float* __restrict__ gamma,
                            const float* __restrict__ beta, float invN,
                            float* __restrict__ extout, int total4, int N) {
    __shared__ float nsc[D], nsh[D];
    int tid = threadIdx.x;
    if (tid < D) {
        float mu  = g_sum[phase][tid] * invN;
        float var = g_sq[phase][tid] * invN - mu * mu;
        float inv = rsqrtf(var + 1e-5f);
        float sc  = __ldg(&gamma[tid]) * inv;
        nsc[tid] = sc;
        nsh[tid] = __ldg(&beta[tid]) - mu * sc;
    }
    __syncthreads();
    int i = blockIdx.x * blockDim.x + tid;
    if (i < N) g_cnt[i] = 0;            // restore invariant for next run
    if (i >= total4) return;
    int c4 = i & 31;
    float4 v  = ((const float4*)h)[i];
    float4 sc = ((const float4*)nsc)[c4];
    float4 sh = ((const float4*)nsh)[c4];
    float4 o;
    o.x = fmaxf(v.x * sc.x + sh.x, 0.f);
    o.y = fmaxf(v.y * sc.y + sh.y, 0.f);
    o.z = fmaxf(v.z * sc.z + sh.z, 0.f);
    o.w = fmaxf(v.w * sc.w + sh.w, 0.f);
    ((float4*)extout)[i] = o;
}

// ---------------------------------------------------------------------------
extern "C" void kernel_launch(void* const* d_in, const int* in_sizes, int n_in,
                              void* d_out, int out_size) {
    const float* x   = (const float*)d_in[0];
    const void*  ei  = d_in[1];
    const float* eps = (const float*)d_in[2];
    const float* W1  = (const float*)d_in[3];
    const float* b1  = (const float*)d_in[4];
    const float* g1  = (const float*)d_in[5];
    const float* be1 = (const float*)d_in[6];
    const float* W2  = (const float*)d_in[7];
    const float* b2  = (const float*)d_in[8];
    const float* g2  = (const float*)d_in[9];
    const float* be2 = (const float*)d_in[10];

    int N = in_sizes[0] / D;
    int E = in_sizes[1] / 2;
    int total4 = N * (D / 4);
    const int TB = 256;

    float* buf0;
    float* buf1;
    cudaGetSymbolAddress((void**)&buf0, g_buf0);
    cudaGetSymbolAddress((void**)&buf1, g_buf1);

    cudaFuncSetAttribute(gemm_tc, cudaFuncAttributeMaxDynamicSharedMemorySize,
                         SMEM_TOTAL);

    int xblk = (total4 + 255) / 256;        // x->fp16 conversion coverage
    int sblk = xblk > 128 ? xblk : 128;     // also covers W split

    setup_kernel<<<sblk, 256>>>((const long long*)ei, E, N, W1, W2, x, total4);
    bucket_kernel<<<(E + 255) / 256, 256>>>(ei, E);
    aggregate_kernel<<<(N * 32 + TB - 1) / TB, TB>>>(x, eps, N);

    int gblocks = (N + BM - 1) / BM;
    float invN = 1.0f / (float)N;

    // layer 1: h1 = g_buf0 @ W1 + b1 (stats fused)
    gemm_tc<<<gblocks, 256, SMEM_TOTAL>>>(buf0, 0, b1, buf1, N, 0, -1,
                                          nullptr, nullptr, invN);
    // layer 2: h2 = relu(bn(h1)) @ W2 + b2 (bn params from g_sum[0] per-block)
    gemm_tc<<<gblocks, 256, SMEM_TOTAL>>>(buf1, 1, b2, buf0, N, 1, 0,
                                          g1, be1, invN);
    // final: d_out = relu(bn(h2)) + g_cnt re-zero
    norm_kernel<<<(total4 + TB - 1) / TB, TB>>>(buf0, 1, g2, be2, invN,
                                                (float*)d_out, total4, N);
}